// round 4
// baseline (speedup 1.0000x reference)
#include <cuda_runtime.h>
#include <cuda_bf16.h>
#include <cstdint>

constexpr int B  = 64;
constexpr int S  = 2048;
constexpr int D  = 512;
constexpr int NM = 1536;
constexpr int NU = 512;
constexpr int VEC = D / 4;          // 128 float4 per row
constexpr int TOTAL_ROWS = B * S;   // 131072 rows in the full tensor
constexpr float ALPHA = 0.1f;

// per-row combined weight, built by phase 1 (512 KB scratch)
__device__ float g_w[TOTAL_ROWS];

// ---------------- Phase 1: histogram -> weights ----------------
__global__ void build_weights_kernel(const int* __restrict__ mask_id,
                                     const int* __restrict__ unmask_id,
                                     float* __restrict__ out)
{
    __shared__ int cm[S];
    __shared__ int cu[S];
    const int b   = blockIdx.x;
    const int tid = threadIdx.x;
    const int nt  = blockDim.x;

    for (int i = tid; i < S; i += nt) { cm[i] = 0; cu[i] = 0; }
    __syncthreads();

    for (int i = tid; i < NM; i += nt)
        atomicAdd(&cm[mask_id[b * NM + i]], 1);
    for (int i = tid; i < NU; i += nt)
        atomicAdd(&cu[unmask_id[b * NU + i]], 1);
    __syncthreads();

    const float wm = 1.0f / ((float)B * (float)NM * (float)D);
    const float wu = ALPHA / ((float)B * (float)NU * (float)D);
    for (int i = tid; i < S; i += nt)
        g_w[b * S + i] = (float)cm[i] * wm + (float)cu[i] * wu;

    if (b == 0 && tid == 0) *out = 0.0f;   // replaces memset node
}

// ---------------- Phase 2: ordered weighted sweep ----------------
__device__ __forceinline__ float sq4(const float4& p, const float4& t) {
    float dx = p.x - t.x, dy = p.y - t.y, dz = p.z - t.z, dw = p.w - t.w;
    return dx * dx + dy * dy + dz * dz + dw * dw;
}

__global__ void weighted_mse_kernel(const float4* __restrict__ pred,
                                    const float4* __restrict__ tgt,
                                    float* __restrict__ out)
{
    const int lane   = threadIdx.x & 31;
    const int warp   = (blockIdx.x * blockDim.x + threadIdx.x) >> 5;
    const int nwarps = (gridDim.x * blockDim.x) >> 5;

    float acc = 0.0f;

    // software-pipeline the (L2-resident) weight load
    int r = warp;
    float wnext = (r < TOTAL_ROWS) ? g_w[r] : 0.0f;

    for (; r < TOTAL_ROWS; r += nwarps) {
        const float w = wnext;
        const int rn = r + nwarps;
        wnext = (rn < TOTAL_ROWS) ? g_w[rn] : 0.0f;

        if (w != 0.0f) {
            const size_t base = (size_t)r * VEC + lane;
            const float4* __restrict__ p = pred + base;
            const float4* __restrict__ t = tgt + base;

            const float4 p0 = p[0],  p1 = p[32], p2 = p[64], p3 = p[96];
            const float4 t0 = t[0],  t1 = t[32], t2 = t[64], t3 = t[96];

            acc += w * (sq4(p0, t0) + sq4(p1, t1) + sq4(p2, t2) + sq4(p3, t3));
        }
    }

    #pragma unroll
    for (int off = 16; off > 0; off >>= 1)
        acc += __shfl_xor_sync(0xFFFFFFFFu, acc, off);

    __shared__ float swarp[8];
    const int wib = threadIdx.x >> 5;
    if (lane == 0) swarp[wib] = acc;
    __syncthreads();
    if (threadIdx.x == 0) {
        float s = 0.0f;
        #pragma unroll
        for (int i = 0; i < 8; i++) s += swarp[i];
        atomicAdd(out, s);
    }
}

extern "C" void kernel_launch(void* const* d_in, const int* in_sizes, int n_in,
                              void* d_out, int out_size)
{
    const float4* pred      = (const float4*)d_in[0];
    const float4* tgt       = (const float4*)d_in[1];
    const int*    mask_id   = (const int*)d_in[2];
    const int*    unmask_id = (const int*)d_in[3];
    float*        out       = (float*)d_out;

    build_weights_kernel<<<B, 512>>>(mask_id, unmask_id, out);

    const int grid = 148 * 8;   // 1184 blocks * 8 warps = 9472 warps
    weighted_mse_kernel<<<grid, 256>>>(pred, tgt, out);
}

// round 5
// speedup vs baseline: 1.1827x; 1.1827x over previous
#include <cuda_runtime.h>
#include <cuda_bf16.h>
#include <cstdint>

// Problem shape (fixed for this dataset entry)
constexpr int B  = 64;
constexpr int S  = 2048;
constexpr int D  = 512;
constexpr int NM = 1536;   // masked indices per sample
constexpr int NU = 512;    // unmasked indices per sample
constexpr int VEC = D / 4; // 128 float4 per row
constexpr int TOTAL_ROWS = B * (NM + NU); // 131072 row tasks
constexpr float ALPHA = 0.1f;

constexpr int GRID = 148 * 8;   // 1184 blocks

// device-side accumulator + completion ticket (self-resetting across graph replays)
__device__ float        g_acc  = 0.0f;
__device__ unsigned int g_done = 0u;

__device__ __forceinline__ float sq4(const float4& p, const float4& t) {
    float dx = p.x - t.x, dy = p.y - t.y, dz = p.z - t.z, dw = p.w - t.w;
    return dx * dx + dy * dy + dz * dz + dw * dw;
}

__global__ void mae_loss_kernel(const float4* __restrict__ pred,
                                const float4* __restrict__ tgt,
                                const int* __restrict__ mask_id,
                                const int* __restrict__ unmask_id,
                                float* __restrict__ out)
{
    const float wm = 1.0f / ((float)B * (float)NM * (float)D);
    const float wu = ALPHA / ((float)B * (float)NU * (float)D);

    const int lane   = threadIdx.x & 31;
    const int warp   = (blockIdx.x * blockDim.x + threadIdx.x) >> 5;
    const int nwarps = (gridDim.x * blockDim.x) >> 5;

    float acc = 0.0f;

    // one warp per row: 2048B row = 32 lanes * 4 float4 each
    for (int r = warp; r < TOTAL_ROWS; r += nwarps) {
        const int b = r >> 11;   // / 2048
        const int j = r & 2047;  // % 2048

        int idx;
        float w;
        if (j < NM) {
            idx = mask_id[b * NM + j];
            w   = wm;
        } else {
            idx = unmask_id[b * NU + (j - NM)];
            w   = wu;
        }

        const size_t base = ((size_t)b * S + (size_t)idx) * (size_t)VEC + lane;
        const float4* __restrict__ p = pred + base;
        const float4* __restrict__ t = tgt + base;

        // 8 independent LDG.128, front-batched by ptxas
        const float4 p0 = p[0],  p1 = p[32], p2 = p[64], p3 = p[96];
        const float4 t0 = t[0],  t1 = t[32], t2 = t[64], t3 = t[96];

        acc += w * (sq4(p0, t0) + sq4(p1, t1) + sq4(p2, t2) + sq4(p3, t3));
    }

    // warp reduce
    #pragma unroll
    for (int off = 16; off > 0; off >>= 1)
        acc += __shfl_xor_sync(0xFFFFFFFFu, acc, off);

    // block reduce across 8 warps
    __shared__ float swarp[8];
    const int wib = threadIdx.x >> 5;
    if (lane == 0) swarp[wib] = acc;
    __syncthreads();

    if (threadIdx.x == 0) {
        float s = 0.0f;
        #pragma unroll
        for (int i = 0; i < 8; i++) s += swarp[i];
        atomicAdd(&g_acc, s);

        // last block publishes the result and resets state for the next replay
        __threadfence();
        unsigned int ticket = atomicAdd(&g_done, 1u);
        if (ticket == (unsigned int)(GRID - 1)) {
            *out  = g_acc;
            g_acc = 0.0f;
            g_done = 0u;
        }
    }
}

extern "C" void kernel_launch(void* const* d_in, const int* in_sizes, int n_in,
                              void* d_out, int out_size)
{
    const float4* pred      = (const float4*)d_in[0];
    const float4* tgt       = (const float4*)d_in[1];
    const int*    mask_id   = (const int*)d_in[2];
    const int*    unmask_id = (const int*)d_in[3];
    float*        out       = (float*)d_out;

    mae_loss_kernel<<<GRID, 256>>>(pred, tgt, mask_id, unmask_id, out);
}